// round 1
// baseline (speedup 1.0000x reference)
#include <cuda_runtime.h>

#define HH 128
#define WW 128
#define CC 392
#define KPOOL 7
#define KK 49
#define MAXN 2048

// Scratch (device globals; no allocation allowed)
__device__ float g_map[HH * WW * CC];            // conv output, [H,W,C]
__device__ float g_off[MAXN * KK * 8];           // per (n,bin): [g][2] offsets in FEATURE coords

// ---------------------------------------------------------------------------
// 3x3 SAME conv, NHWC fp32. Block: 64 pixels (one row segment) x 64 couts.
// ---------------------------------------------------------------------------
__global__ __launch_bounds__(256) void conv3x3_kernel(const float* __restrict__ f,
                                                      const float* __restrict__ w)
{
    __shared__ float As[8][68];   // [k][m], padded: store bank = (4k+m)%32, conflict-free
    __shared__ float Bs[8][64];   // [k][n]

    const int y   = blockIdx.x >> 1;
    const int x0  = (blockIdx.x & 1) << 6;
    const int co0 = blockIdx.y << 6;
    const int tid = threadIdx.x;
    const int tm  = tid >> 4;     // 0..15
    const int tn  = tid & 15;     // 0..15

    float acc[4][4];
#pragma unroll
    for (int i = 0; i < 4; ++i)
#pragma unroll
        for (int j = 0; j < 4; ++j) acc[i][j] = 0.f;

    const int a_k  = tid & 7;     // ci-within-chunk
    const int a_m0 = tid >> 3;    // 0..31 (and +32)
    const int b_k  = tid >> 6;    // 0..3 (and +4)
    const int b_n  = tid & 63;
    const int co_b = co0 + b_n;
    const bool co_ok = (co_b < CC);

#pragma unroll 1
    for (int t = 0; t < 9; ++t) {
        const int dy = t / 3 - 1;
        const int dx = t % 3 - 1;
        const int yy = y + dy;
        const bool yok = (yy >= 0) && (yy < HH);
        const int xbase = x0 + dx + a_m0;
#pragma unroll 1
        for (int ci0 = 0; ci0 < CC; ci0 += 8) {
            __syncthreads();
            // A tile: As[k][m] = f[yy, x0+dx+m, ci0+k]  (zero pad)
            {
                float v0 = 0.f, v1 = 0.f;
                if (yok) {
                    const float* frow = f + (yy * WW) * CC + ci0 + a_k;
                    int xx0 = xbase;
                    int xx1 = xbase + 32;
                    if (xx0 >= 0 && xx0 < WW) v0 = __ldg(frow + xx0 * CC);
                    if (xx1 >= 0 && xx1 < WW) v1 = __ldg(frow + xx1 * CC);
                }
                As[a_k][a_m0]      = v0;
                As[a_k][a_m0 + 32] = v1;
            }
            // B tile: Bs[k][n] = w[t, ci0+k, co0+n]
            {
                float v0 = 0.f, v1 = 0.f;
                if (co_ok) {
                    const float* wp = w + (size_t)(t * CC + ci0) * CC + co_b;
                    v0 = __ldg(wp + (size_t)b_k * CC);
                    v1 = __ldg(wp + (size_t)(b_k + 4) * CC);
                }
                Bs[b_k][b_n]     = v0;
                Bs[b_k + 4][b_n] = v1;
            }
            __syncthreads();
#pragma unroll
            for (int k = 0; k < 8; ++k) {
                float4 a = *(const float4*)&As[k][tm * 4];
                float4 b = *(const float4*)&Bs[k][tn * 4];
                acc[0][0] = fmaf(a.x, b.x, acc[0][0]);
                acc[0][1] = fmaf(a.x, b.y, acc[0][1]);
                acc[0][2] = fmaf(a.x, b.z, acc[0][2]);
                acc[0][3] = fmaf(a.x, b.w, acc[0][3]);
                acc[1][0] = fmaf(a.y, b.x, acc[1][0]);
                acc[1][1] = fmaf(a.y, b.y, acc[1][1]);
                acc[1][2] = fmaf(a.y, b.z, acc[1][2]);
                acc[1][3] = fmaf(a.y, b.w, acc[1][3]);
                acc[2][0] = fmaf(a.z, b.x, acc[2][0]);
                acc[2][1] = fmaf(a.z, b.y, acc[2][1]);
                acc[2][2] = fmaf(a.z, b.z, acc[2][2]);
                acc[2][3] = fmaf(a.z, b.w, acc[2][3]);
                acc[3][0] = fmaf(a.w, b.x, acc[3][0]);
                acc[3][1] = fmaf(a.w, b.y, acc[3][1]);
                acc[3][2] = fmaf(a.w, b.z, acc[3][2]);
                acc[3][3] = fmaf(a.w, b.w, acc[3][3]);
            }
        }
    }

#pragma unroll
    for (int i = 0; i < 4; ++i) {
        const int px = y * WW + x0 + tm * 4 + i;
#pragma unroll
        for (int j = 0; j < 4; ++j) {
            int co = co0 + tn * 4 + j;
            if (co < CC) g_map[(size_t)px * CC + co] = acc[i][j];
        }
    }
}

// ---------------------------------------------------------------------------
// Kernel 2: PS-RoI pool of the conv output -> per-bin offsets (feature coords)
// ---------------------------------------------------------------------------
__global__ __launch_bounds__(256) void offset_pool_kernel(const float* __restrict__ rois, int N)
{
    int idx = blockIdx.x * blockDim.x + threadIdx.x;   // (n*49 + bin)
    if (idx >= N * KK) return;
    int n   = idx / KK;
    int bin = idx - n * KK;
    int bi  = bin / KPOOL;   // row i
    int bj  = bin - bi * KPOOL;

    const float* r = rois + n * 5;
    float r1 = r[1], r2 = r[2], r3 = r[3], r4 = r[4];
    float x1 = r1 * 0.0625f;
    float y1 = r2 * 0.0625f;
    float x2 = (r3 + 1.0f) * 0.0625f;
    float y2 = (r4 + 1.0f) * 0.0625f;
    float bw = (x2 - x1) / 7.0f;
    float bh = (y2 - y1) / 7.0f;
    float cx = x1 + ((float)bj + 0.5f) * bw;
    float cy = y1 + ((float)bi + 0.5f) * bh;

    float y0f = floorf(cy), x0f = floorf(cx);
    float wy = cy - y0f,    wx = cx - x0f;
    int iy0 = min(max((int)y0f, 0), HH - 1);
    int iy1 = min(max((int)y0f + 1, 0), HH - 1);
    int ix0 = min(max((int)x0f, 0), WW - 1);
    int ix1 = min(max((int)x0f + 1, 0), WW - 1);

    float w00 = (1.f - wy) * (1.f - wx);
    float w01 = (1.f - wy) * wx;
    float w10 = wy * (1.f - wx);
    float w11 = wy * wx;

    const float* p00 = g_map + ((size_t)(iy0 * WW + ix0)) * CC + bin * 8;
    const float* p01 = g_map + ((size_t)(iy0 * WW + ix1)) * CC + bin * 8;
    const float* p10 = g_map + ((size_t)(iy1 * WW + ix0)) * CC + bin * 8;
    const float* p11 = g_map + ((size_t)(iy1 * WW + ix1)) * CC + bin * 8;

    float rw = r3 - r1 + 1.0f;
    float rh = r4 - r2 + 1.0f;

    float* o = g_off + (size_t)idx * 8;
#pragma unroll
    for (int g = 0; g < 4; ++g) {
        int d0 = g * 2, d1 = g * 2 + 1;
        float px = w00 * p00[d0] + w01 * p01[d0] + w10 * p10[d0] + w11 * p11[d0];
        float py = w00 * p00[d1] + w01 * p01[d1] + w10 * p10[d1] + w11 * p11[d1];
        // off_img = pooled * roi_{w,h} * 0.1 ; stored /16 (exact) -> feature coords
        float ox = (px * rw) * 0.1f * 0.0625f;
        float oy = (py * rh) * 0.1f * 0.0625f;
        o[d0] = ox;
        o[d1] = oy;
    }
}

// ---------------------------------------------------------------------------
// Kernel 3: deformable PS-RoI pool of the raw features -> output [N,8,7,7]
// ---------------------------------------------------------------------------
__global__ __launch_bounds__(256) void deform_pool_kernel(const float* __restrict__ f,
                                                          const float* __restrict__ rois,
                                                          float* __restrict__ out, int N)
{
    int idx = blockIdx.x * blockDim.x + threadIdx.x;   // ((n*49+bin)*8 + d)
    if (idx >= N * KK * 8) return;
    int d   = idx & 7;
    int nb  = idx >> 3;        // n*49+bin
    int n   = nb / KK;
    int bin = nb - n * KK;
    int bi  = bin / KPOOL;
    int bj  = bin - bi * KPOOL;

    const float* r = rois + n * 5;
    float x1 = r[1] * 0.0625f;
    float y1 = r[2] * 0.0625f;
    float x2 = (r[3] + 1.0f) * 0.0625f;
    float y2 = (r[4] + 1.0f) * 0.0625f;
    float bw = (x2 - x1) / 7.0f;
    float bh = (y2 - y1) / 7.0f;
    float cx = x1 + ((float)bj + 0.5f) * bw;
    float cy = y1 + ((float)bi + 0.5f) * bh;

    int g = d >> 1;
    const float* o = g_off + (size_t)nb * 8 + g * 2;
    float sx = cx + o[0];
    float sy = cy + o[1];

    float y0f = floorf(sy), x0f = floorf(sx);
    float wy = sy - y0f,    wx = sx - x0f;
    int iy0 = min(max((int)y0f, 0), HH - 1);
    int iy1 = min(max((int)y0f + 1, 0), HH - 1);
    int ix0 = min(max((int)x0f, 0), WW - 1);
    int ix1 = min(max((int)x0f + 1, 0), WW - 1);

    int ch = bin * 8 + d;
    float v00 = __ldg(f + ((size_t)(iy0 * WW + ix0)) * CC + ch);
    float v01 = __ldg(f + ((size_t)(iy0 * WW + ix1)) * CC + ch);
    float v10 = __ldg(f + ((size_t)(iy1 * WW + ix0)) * CC + ch);
    float v11 = __ldg(f + ((size_t)(iy1 * WW + ix1)) * CC + ch);

    float val = (1.f - wy) * (1.f - wx) * v00 + (1.f - wy) * wx * v01
              + wy * (1.f - wx) * v10 + wy * wx * v11;

    // out[n, d, i, j] with d = g*2+c ; bin = i*7+j
    out[((size_t)n * 8 + d) * KK + bin] = val;
}

// ---------------------------------------------------------------------------
extern "C" void kernel_launch(void* const* d_in, const int* in_sizes, int n_in,
                              void* d_out, int out_size)
{
    const float* features = (const float*)d_in[0];  // [1,128,128,392]
    const float* rois     = (const float*)d_in[1];  // [N,5]
    const float* conv_w   = (const float*)d_in[2];  // [3,3,392,392]
    float* out = (float*)d_out;
    int N = in_sizes[1] / 5;

    dim3 gconv(256, 7);
    conv3x3_kernel<<<gconv, 256>>>(features, conv_w);

    int t2 = N * KK;
    offset_pool_kernel<<<(t2 + 255) / 256, 256>>>(rois, N);

    int t3 = N * KK * 8;
    deform_pool_kernel<<<(t3 + 255) / 256, 256>>>(features, rois, out, N);
}